// round 10
// baseline (speedup 1.0000x reference)
#include <cuda_runtime.h>
#include <cuda_bf16.h>
#include <math.h>
#include <stdint.h>

#define B_ 4
#define T_ 40
#define R_ 2000
#define A_ 36864
#define H_ 64
#define W_ 64
#define C_ 256
#define PP_ 7
#define NCLS_ 21
#define NPOS_ 64
#define NNEG_ 192
#define DH_ 1024
#define D_ (PP_*PP_*C_)   // 12544
#define KT_ 8             // split-K factor
#define KPC_ (D_/KT_)     // 1568 per CTA
#define BK_ 32
#define NIT_ (KPC_/BK_)   // 49

// GEMM smem: A tiles bf16 rows padded to 40 elems (80B); B tile fp32 rows padded to 68 words
#define TPAD_ 40
#define ATILE_ (128*TPAD_*2)            // 10240
#define BPADW_ 68
#define BTILEF_ (32*BPADW_*4)           // 8704
#define STAGE_ (2*ATILE_ + BTILEF_)     // 29184
#define NSTG_ 3
#define SMEM_GEMM_ (NSTG_*STAGE_)       // 87552

// ---------------- scratch ----------------
__device__ float g_fmt[B_*H_*W_*C_];
__device__ float g_maxiou[B_*A_];
__device__ int   g_tidx[B_*A_];
__device__ float g_ioum[B_*R_];
__device__ int   g_ridx[B_*R_];
__device__ int   g_pos[128];
__device__ int   g_neg[252];
__device__ int   g_posr[NPOS_];
__device__ int   g_negr[NNEG_];
__device__ int   g_cntP[18], g_cntN[18];
__device__ int   g_cntReady;
__device__ int   g_selDone;
__device__ int   g_tileCnt[32];
__device__ __nv_bfloat16 g_Ahi[256*D_];
__device__ __nv_bfloat16 g_Alo[256*D_];
__device__ float g_partial[KT_][256*DH_];
__device__ float g_hmid[256*DH_];
__device__ float g_rreg[256*4];
__device__ float g_rcls[256*NCLS_];

__device__ __forceinline__ uint32_t smem_u32(const void* p) {
    uint32_t a;
    asm("{ .reg .u64 t; cvta.to.shared.u64 t, %1; cvt.u32.u64 %0, t; }" : "=r"(a) : "l"(p));
    return a;
}
__device__ __forceinline__ unsigned fkey(float f) {
    unsigned u = __float_as_uint(f);
    return (u & 0x80000000u) ? ~u : (u | 0x80000000u);
}

// ---------------- fused prep: init | transpose | rpn_iou | rcnn_iou ----------------
#define PB_TRANS 4096                   // 2*8*256
#define PB_RPN   288                    // 72*4 (2 anchors/thread)
#define PB_RCNN  32                     // 8*4
#define PB_TOTAL (PB_TRANS + PB_RPN + PB_RCNN + 1)

__global__ void prep_kernel(const float* __restrict__ fm,
                            const float* __restrict__ bboxes,
                            const float* __restrict__ anchors,
                            const float* __restrict__ nms_reg) {
    __shared__ float tile[32][33];
    __shared__ float sar[T_];
    int blk = blockIdx.x;
    int tid = threadIdx.x;          // 256
    if (blk < PB_TRANS) {
        int bh = blk >> 4;
        int sub = blk & 15;
        int x0 = (sub & 1) * 32, c0 = (sub >> 1) * 32;
        int b = bh >> 6, y = bh & 63;
        int tx = tid & 31, ty = tid >> 5;
        #pragma unroll
        for (int i = 0; i < 4; i++) {
            int c = c0 + ty + i*8;
            tile[ty + i*8][tx] = fm[((b*C_ + c)*H_ + y)*W_ + x0 + tx];
        }
        __syncthreads();
        #pragma unroll
        for (int i = 0; i < 4; i++) {
            int xr = ty + i*8;
            g_fmt[((b*H_ + y)*W_ + x0+xr)*C_ + c0+tx] = tile[tx][xr];
        }
        return;
    }
    blk -= PB_TRANS;
    if (blk < PB_RPN) {
        int b = blk / 72, bx = blk % 72;
        float* sb = &tile[0][0];
        if (tid < T_*4) sb[tid] = bboxes[b*T_*4 + tid];
        __syncthreads();
        if (tid < T_) {
            float bt = sb[tid*4+0], bl = sb[tid*4+1], bb = sb[tid*4+2], br = sb[tid*4+3];
            sar[tid] = (bb-bt)*(br-bl);
        }
        __syncthreads();
        int a0 = bx*512 + tid;
        float4 an0 = ((const float4*)anchors)[a0];
        float4 an1 = ((const float4*)anchors)[a0 + 256];
        float ar0 = (an0.z-an0.x)*(an0.w-an0.y);
        float ar1 = (an1.z-an1.x)*(an1.w-an1.y);
        float best0 = -1.0f, best1 = -1.0f; int bi0 = 0, bi1 = 0;
        #pragma unroll 4
        for (int t = 0; t < T_; t++) {
            float bt = sb[t*4+0], bl = sb[t*4+1], bb = sb[t*4+2], br = sb[t*4+3];
            float a1 = sar[t];
            float in0 = fmaxf(fminf(bb,an0.z)-fmaxf(bt,an0.x),0.f)
                      * fmaxf(fminf(br,an0.w)-fmaxf(bl,an0.y),0.f);
            float iou0 = in0 / (a1 + ar0 - in0);
            if (iou0 > best0) { best0 = iou0; bi0 = t; }
            float in1 = fmaxf(fminf(bb,an1.z)-fmaxf(bt,an1.x),0.f)
                      * fmaxf(fminf(br,an1.w)-fmaxf(bl,an1.y),0.f);
            float iou1 = in1 / (a1 + ar1 - in1);
            if (iou1 > best1) { best1 = iou1; bi1 = t; }
        }
        g_maxiou[b*A_+a0] = best0;       g_tidx[b*A_+a0] = bi0;
        g_maxiou[b*A_+a0+256] = best1;   g_tidx[b*A_+a0+256] = bi1;
        return;
    }
    blk -= PB_RPN;
    if (blk < PB_RCNN) {
        int b = blk >> 3, rx = blk & 7;
        float* sb = &tile[0][0];
        if (tid < T_*4) sb[tid] = bboxes[b*T_*4 + tid];
        __syncthreads();
        int r = rx*256 + tid;
        if (r >= R_) return;
        float4 nr4 = ((const float4*)nms_reg)[b*R_+r];
        float area1 = (nr4.z-nr4.x)*(nr4.w-nr4.y);
        float best = -1.0f; int bi = 0;
        #pragma unroll 4
        for (int t = 0; t < T_; t++) {
            float bt = sb[t*4+0], bl = sb[t*4+1], bb = sb[t*4+2], br = sb[t*4+3];
            float inter = fmaxf(fminf(bb,nr4.z)-fmaxf(bt,nr4.x),0.f)
                        * fmaxf(fminf(br,nr4.w)-fmaxf(bl,nr4.y),0.f);
            float a2 = (bb-bt)*(br-bl);
            float iou = inter / (area1 + a2 - inter);
            if (iou > best) { best = iou; bi = t; }
        }
        g_ioum[b*R_+r] = best;
        g_ridx[b*R_+r] = bi;
        return;
    }
    // init block
    if (tid < 128)  g_pos[tid]  = 0;
    if (tid < 252)  g_neg[tid]  = 0;
    if (tid < NPOS_) g_posr[tid] = 0;
    if (tid < 32)   g_tileCnt[tid] = 0;
    if (tid == 0) { g_cntReady = 0; g_selDone = 0; }
}

// ============ fused selection: rpn(blocks 0-17) | topk+posr(18) | roi(19-82) ============
#define SEL_RPN_ 18
#define SEL_TOPK_ 18
#define SEL_ROI0_ 19
#define SEL_NBLK_ 83

__global__ void __launch_bounds__(1024, 2) sel_kernel(const float* __restrict__ nms_reg) {
    __shared__ float sv[B_*R_];           // topk values
    __shared__ int hist[256];
    __shared__ int sS[256];
    __shared__ int sCnt[32], sOff[32], sCnt2[32], sOff2[32];
    __shared__ int sTot, sTot2;
    __shared__ unsigned sPrefix;
    __shared__ int sRemain, sCntG;
    __shared__ int sBaseP, sBaseN;

    int blk = blockIdx.x;
    int tid = threadIdx.x, lane = tid & 31, wid = tid >> 5;

    if (blk < SEL_RPN_) {
        // ---- RPN chunk: count, publish, wait, place ----
        int c = blk;
        int cp = 0;
        float v8[8];
        #pragma unroll
        for (int i = 0; i < 8; i++) {
            v8[i] = g_maxiou[c*8192 + i*1024 + tid];
            cp += (v8[i] > 0.5f) ? 1 : 0;
        }
        #pragma unroll
        for (int d = 16; d; d >>= 1) cp += __shfl_down_sync(0xffffffffu, cp, d);
        if (lane == 0) sCnt[wid] = cp;
        __syncthreads();
        if (wid == 0) {
            int s = sCnt[lane];
            #pragma unroll
            for (int d = 16; d; d >>= 1) s += __shfl_down_sync(0xffffffffu, s, d);
            if (lane == 0) {
                g_cntP[c] = s; g_cntN[c] = 8192 - s;
                __threadfence();
                atomicAdd(&g_cntReady, 1);
            }
        }
        if (tid == 0) {
            while (atomicAdd(&g_cntReady, 0) < 18) {}
            int bp = 0, bn = 0;
            for (int i = 0; i < c; i++) { bp += g_cntP[i]; bn += g_cntN[i]; }
            sBaseP = bp; sBaseN = bn;
        }
        __syncthreads();
        int baseP = sBaseP, baseN = sBaseN;
        if (baseP >= 128 && baseN >= 252) return;
        for (int ph = 0; ph < 8; ph++) {
            int j = c*8192 + ph*1024 + tid;
            bool fp = (v8[ph] > 0.5f), fn = !fp;
            unsigned mp = __ballot_sync(0xffffffffu, fp);
            unsigned mn = __ballot_sync(0xffffffffu, fn);
            if (lane == 0) { sCnt[wid] = __popc(mp); sCnt2[wid] = __popc(mn); }
            __syncthreads();
            if (wid == 0) {
                int cp2 = sCnt[lane], cn2 = sCnt2[lane];
                int sp = cp2, sn = cn2;
                #pragma unroll
                for (int d = 1; d < 32; d <<= 1) {
                    int tp = __shfl_up_sync(0xffffffffu, sp, d);
                    int tn = __shfl_up_sync(0xffffffffu, sn, d);
                    if (lane >= d) { sp += tp; sn += tn; }
                }
                sOff[lane] = sp - cp2; sOff2[lane] = sn - cn2;
                if (lane == 31) { sTot = sp; sTot2 = sn; }
            }
            __syncthreads();
            if (fp) {
                int p = baseP + sOff[wid] + __popc(mp & ((1u << lane) - 1u));
                if (p < 128) g_pos[p] = j;
            }
            if (fn) {
                int p = baseN + sOff2[wid] + __popc(mn & ((1u << lane) - 1u));
                if (p < 252) g_neg[p] = j;
            }
            baseP += sTot; baseN += sTot2;
            __syncthreads();
            if (baseP >= 128 && baseN >= 252) return;
        }
        return;
    }

    if (blk == SEL_TOPK_) {
        // ---- topk(192) radix-select + posr first-64 ----
        for (int j = tid; j < B_*R_; j += 1024) {
            float v = g_ioum[j];
            sv[j] = (v <= 0.5f) ? v : -INFINITY;
        }
        if (tid == 0) { sPrefix = 0; sRemain = NNEG_; sCntG = 0; }
        __syncthreads();

        // posr: first 64 with iou > 0.5, index order
        int base = 0;
        for (int ph = 0; ph < 8 && base < NPOS_; ph++) {
            int j = ph*1024 + tid;
            bool f = (j < B_*R_) && (g_ioum[j] > 0.5f);
            unsigned m = __ballot_sync(0xffffffffu, f);
            if (lane == 0) sCnt[wid] = __popc(m);
            __syncthreads();
            if (wid == 0) {
                int cp = sCnt[lane], sp = cp;
                #pragma unroll
                for (int d = 1; d < 32; d <<= 1) {
                    int tp = __shfl_up_sync(0xffffffffu, sp, d);
                    if (lane >= d) sp += tp;
                }
                sOff[lane] = sp - cp;
                if (lane == 31) sTot = sp;
            }
            __syncthreads();
            if (f) {
                int p = base + sOff[wid] + __popc(m & ((1u << lane) - 1u));
                if (p < NPOS_) g_posr[p] = j;
            }
            base += sTot;
            __syncthreads();
        }

        // radix select threshold key (top-192, ties -> lowest index)
        for (int lvl = 24; lvl >= 0; lvl -= 8) {
            if (tid < 256) hist[tid] = 0;
            __syncthreads();
            unsigned pfx = sPrefix;
            int need = sRemain;
            for (int j = tid; j < B_*R_; j += 1024) {
                unsigned k = fkey(sv[j]);
                bool match = (lvl == 24) || ((k >> (lvl+8)) == pfx);
                if (match) atomicAdd(&hist[(k >> lvl) & 255], 1);
            }
            __syncthreads();
            if (tid < 256) sS[tid] = hist[tid];
            __syncthreads();
            #pragma unroll
            for (int d = 1; d < 256; d <<= 1) {
                int v = 0;
                if (tid < 256 && tid + d < 256) v = sS[tid + d];
                __syncthreads();
                if (tid < 256) sS[tid] += v;
                __syncthreads();
            }
            if (tid < 256) {
                int Sb = sS[tid];
                int Snext = (tid < 255) ? sS[tid+1] : 0;
                if (Sb >= need && Snext < need) {
                    sPrefix = (pfx << 8) | (unsigned)tid;
                    sRemain = need - Snext;
                }
            }
            __syncthreads();
        }
        unsigned K = sPrefix;
        int needEq = sRemain;
        int G = NNEG_ - needEq;

        for (int j = tid; j < B_*R_; j += 1024) {
            if (fkey(sv[j]) > K) {
                int p = atomicAdd(&sCntG, 1);
                g_negr[p] = j;
            }
        }
        __syncthreads();
        base = 0;
        for (int ph = 0; ph < 8 && base < needEq; ph++) {
            int j = ph*1024 + tid;
            bool f = (j < B_*R_) && (fkey(sv[j]) == K);
            unsigned m = __ballot_sync(0xffffffffu, f);
            if (lane == 0) sCnt[wid] = __popc(m);
            __syncthreads();
            if (wid == 0) {
                int cp = sCnt[lane], sp = cp;
                #pragma unroll
                for (int d = 1; d < 32; d <<= 1) {
                    int tp = __shfl_up_sync(0xffffffffu, sp, d);
                    if (lane >= d) sp += tp;
                }
                sOff[lane] = sp - cp;
                if (lane == 31) sTot = sp;
            }
            __syncthreads();
            if (f) {
                int p = base + sOff[wid] + __popc(m & ((1u << lane) - 1u));
                if (p < needEq) g_negr[G + p] = j;
            }
            base += sTot;
            __syncthreads();
        }
        __syncthreads();
        if (tid == 0) {
            __threadfence();
            atomicExch(&g_selDone, 1);
        }
        return;
    }

    // ---- ROI pool: 4 rois per block, spin on topk done ----
    if (tid == 0) {
        while (atomicAdd(&g_selDone, 0) == 0) {}
    }
    __syncthreads();
    int j = (blk - SEL_ROI0_) * 4 + (tid >> 8);
    int c = tid & 255;
    int sel = (j < NPOS_) ? g_posr[j] : g_negr[j - NPOS_];
    int b = sel / R_;
    float t  = nms_reg[sel*4+0], l = nms_reg[sel*4+1];
    float bb = nms_reg[sel*4+2], r = nms_reg[sel*4+3];
    const float* fb = g_fmt + (size_t)b * H_ * W_ * C_;
    for (int p = 0; p < PP_*PP_; p++) {
        int py = p / PP_, px = p % PP_;
        float gy = (py + 0.5f) / (float)PP_;
        float gx = (px + 0.5f) / (float)PP_;
        float y = fminf(fmaxf(t + gy * (bb - t), 0.f), (float)(H_-1));
        float x = fminf(fmaxf(l + gx * (r  - l), 0.f), (float)(W_-1));
        int y0 = (int)floorf(y), x0 = (int)floorf(x);
        int y1 = min(y0 + 1, H_-1), x1 = min(x0 + 1, W_-1);
        float wy = y - (float)y0, wx = x - (float)x0;
        float v00 = fb[(y0*W_+x0)*C_ + c];
        float v01 = fb[(y0*W_+x1)*C_ + c];
        float v10 = fb[(y1*W_+x0)*C_ + c];
        float v11 = fb[(y1*W_+x1)*C_ + c];
        float v = v00*(1.f-wy)*(1.f-wx) + v01*(1.f-wy)*wx
                + v10*wy*(1.f-wx)       + v11*wy*wx;
        __nv_bfloat16 h = __float2bfloat16(v);
        int o = j*D_ + p*C_ + c;
        g_Ahi[o] = h;
        g_Alo[o] = __float2bfloat16(v - __bfloat162float(h));
    }
}

// ---------------- mma.sync GEMM: BM128 BN64 BK32, 3-stage, split-K=8 ----------------
// R8's proven 32x32 warp tile; last CTA per (m,n)-tile reduces partials.
__device__ __forceinline__ void ldsm_x4(uint32_t* r, uint32_t addr) {
    asm volatile("ldmatrix.sync.aligned.m8n8.x4.shared.b16 {%0,%1,%2,%3}, [%4];"
        : "=r"(r[0]), "=r"(r[1]), "=r"(r[2]), "=r"(r[3]) : "r"(addr));
}
__device__ __forceinline__ void mma16816(float* d, const uint32_t* a, const uint32_t* b) {
    asm volatile("mma.sync.aligned.m16n8k16.row.col.f32.bf16.bf16.f32 "
        "{%0,%1,%2,%3}, {%4,%5,%6,%7}, {%8,%9}, {%0,%1,%2,%3};"
        : "+f"(d[0]), "+f"(d[1]), "+f"(d[2]), "+f"(d[3])
        : "r"(a[0]), "r"(a[1]), "r"(a[2]), "r"(a[3]), "r"(b[0]), "r"(b[1]));
}
__device__ __forceinline__ void cp16(uint32_t saddr, const void* gaddr) {
    asm volatile("cp.async.cg.shared.global [%0], [%1], 16;" :: "r"(saddr), "l"(gaddr));
}

__global__ void __launch_bounds__(256, 2) gemm_mma_kernel(const float* __restrict__ W1,
                                                          const float* __restrict__ b1) {
    extern __shared__ char smem[];
    uint32_t sb = smem_u32(smem);
    __shared__ int sLast;
    int tid = threadIdx.x, wid = tid >> 5, lane = tid & 31;
    int n0 = blockIdx.x * 64;
    int m0 = blockIdx.y * 128;
    int kt = blockIdx.z;
    int kbase = kt * KPC_;
    int wm = wid >> 1, wn = wid & 1;     // warp tile 32x32

    const uint4* bAhi = (const uint4*)g_Ahi + (size_t)m0 * (D_/8);
    const uint4* bAlo = (const uint4*)g_Alo + (size_t)m0 * (D_/8);

    int a0r = tid >> 2,          a0q = tid & 3;
    int a1r = (tid + 256) >> 2,  a1q = tid & 3;
    int b0r = tid >> 4, b0q = tid & 15;

    auto load_stage = [&](int it) {
        uint32_t sg = sb + (it % NSTG_) * STAGE_;
        int kk = kbase + it*BK_;
        int kq = kk >> 3;
        cp16(sg +          a0r*80 + a0q*16, bAhi + (size_t)a0r*(D_/8) + kq + a0q);
        cp16(sg +          a1r*80 + a1q*16, bAhi + (size_t)a1r*(D_/8) + kq + a1q);
        cp16(sg + ATILE_ + a0r*80 + a0q*16, bAlo + (size_t)a0r*(D_/8) + kq + a0q);
        cp16(sg + ATILE_ + a1r*80 + a1q*16, bAlo + (size_t)a1r*(D_/8) + kq + a1q);
        uint32_t bg = sg + 2*ATILE_;
        cp16(bg + b0r*(BPADW_*4) + b0q*16,      W1 + (size_t)(kk + b0r)*DH_ + n0 + b0q*4);
        cp16(bg + (b0r+16)*(BPADW_*4) + b0q*16, W1 + (size_t)(kk + b0r+16)*DH_ + n0 + b0q*4);
        asm volatile("cp.async.commit_group;");
    };

    float acc[2][4][4];
    #pragma unroll
    for (int i = 0; i < 2; i++)
        #pragma unroll
        for (int j = 0; j < 4; j++)
            #pragma unroll
            for (int q = 0; q < 4; q++) acc[i][j][q] = 0.f;

    load_stage(0);
    load_stage(1);

    for (int it = 0; it < NIT_; it++) {
        asm volatile("cp.async.wait_group 1;");
        __syncthreads();
        if (it + 2 < NIT_) load_stage(it + 2);
        else asm volatile("cp.async.commit_group;");

        uint32_t sg = sb + (it % NSTG_) * STAGE_;
        uint32_t aHiB = sg, aLoB = sg + ATILE_;
        const float* sBf = (const float*)(smem + (it % NSTG_) * STAGE_ + 2*ATILE_);

        #pragma unroll
        for (int ks = 0; ks < 2; ks++) {
            int acol = ks*16 + ((lane >> 4) & 1) * 8;
            uint32_t ahi[2][4], alo[2][4], bhi[4][2], blo[4][2];
            #pragma unroll
            for (int mt = 0; mt < 2; mt++) {
                int arow = wm*32 + mt*16 + (lane & 15);
                uint32_t off = arow*80 + acol*2;
                ldsm_x4(ahi[mt], aHiB + off);
                ldsm_x4(alo[mt], aLoB + off);
            }
            #pragma unroll
            for (int nt = 0; nt < 4; nt++) {
                int nn = wn*32 + nt*8 + (lane >> 2);
                #pragma unroll
                for (int rg = 0; rg < 2; rg++) {
                    int kk2 = ks*16 + (lane & 3)*2 + rg*8;
                    float v0 = sBf[(kk2+0)*BPADW_ + nn];
                    float v1 = sBf[(kk2+1)*BPADW_ + nn];
                    uint32_t hreg;
                    asm("cvt.rn.bf16x2.f32 %0, %1, %2;" : "=r"(hreg) : "f"(v1), "f"(v0));
                    float h0 = __uint_as_float(hreg << 16);
                    float h1 = __uint_as_float(hreg & 0xFFFF0000u);
                    uint32_t lreg;
                    asm("cvt.rn.bf16x2.f32 %0, %1, %2;" : "=r"(lreg) : "f"(v1-h1), "f"(v0-h0));
                    bhi[nt][rg] = hreg;
                    blo[nt][rg] = lreg;
                }
            }
            #pragma unroll
            for (int mt = 0; mt < 2; mt++)
                #pragma unroll
                for (int nt = 0; nt < 4; nt++) {
                    mma16816(acc[mt][nt], ahi[mt], bhi[nt]);
                    mma16816(acc[mt][nt], ahi[mt], blo[nt]);
                    mma16816(acc[mt][nt], alo[mt], bhi[nt]);
                }
        }
    }

    // write split-K partials
    float* outp = g_partial[kt];
    int g = lane >> 2, qc = (lane & 3) * 2;
    #pragma unroll
    for (int mt = 0; mt < 2; mt++) {
        #pragma unroll
        for (int nt = 0; nt < 4; nt++) {
            int row = m0 + wm*32 + mt*16 + g;
            int col = n0 + wn*32 + nt*8 + qc;
            *(float2*)&outp[(size_t)row*DH_ + col]     = make_float2(acc[mt][nt][0], acc[mt][nt][1]);
            *(float2*)&outp[(size_t)(row+8)*DH_ + col] = make_float2(acc[mt][nt][2], acc[mt][nt][3]);
        }
    }
    __threadfence();
    __syncthreads();
    if (tid == 0) sLast = atomicAdd(&g_tileCnt[blockIdx.y*16 + blockIdx.x], 1);
    __syncthreads();
    if (sLast == KT_ - 1) {
        __threadfence();   // acquire: other CTAs' partials visible
        // reduce 128x64 tile: fixed kt order, + bias + relu
        for (int e4 = tid; e4 < 128*16; e4 += 256) {
            int row = m0 + (e4 >> 4);
            int c4 = e4 & 15;
            size_t off = (size_t)row*DH_ + n0 + c4*4;
            float4 s = *(const float4*)&b1[n0 + c4*4];
            #pragma unroll
            for (int k = 0; k < KT_; k++) {
                float4 p = *(const float4*)&g_partial[k][off];
                s.x += p.x; s.y += p.y; s.z += p.z; s.w += p.w;
            }
            float4 o;
            o.x = fmaxf(s.x, 0.f); o.y = fmaxf(s.y, 0.f);
            o.z = fmaxf(s.z, 0.f); o.w = fmaxf(s.w, 0.f);
            *(float4*)&g_hmid[off] = o;
        }
    }
}

// ---------------- heads only (hmid precomputed in GEMM) ----------------
__global__ void __launch_bounds__(1024) mlp_tail_kernel(const float* __restrict__ Wr, const float* __restrict__ br,
                                const float* __restrict__ Wc, const float* __restrict__ bc) {
    __shared__ float h[DH_];
    int row = blockIdx.x;
    int tid = threadIdx.x;              // 1024
    h[tid] = g_hmid[(size_t)row*DH_ + tid];
    __syncthreads();
    int wid = tid >> 5, lane = tid & 31;
    if (wid < 4 + NCLS_) {
        float sum = 0.f;
        if (wid < 4) {
            #pragma unroll 8
            for (int k = lane; k < DH_; k += 32) sum += h[k] * Wr[k*4 + wid];
        } else {
            int oc = wid - 4;
            #pragma unroll 8
            for (int k = lane; k < DH_; k += 32) sum += h[k] * Wc[k*NCLS_ + oc];
        }
        #pragma unroll
        for (int d = 16; d; d >>= 1) sum += __shfl_down_sync(0xffffffffu, sum, d);
        if (lane == 0) {
            if (wid < 4) g_rreg[row*4 + wid] = sum + br[wid];
            else         g_rcls[row*NCLS_ + (wid-4)] = sum + bc[wid-4];
        }
    }
}

// ---------------- finalize ----------------
__device__ float blockReduceSum512(float v, float* sbuf) {
    int tid = threadIdx.x;
    sbuf[tid] = v; __syncthreads();
    for (int s = 256; s > 0; s >>= 1) {
        if (tid < s) sbuf[tid] += sbuf[tid + s];
        __syncthreads();
    }
    float r = sbuf[0]; __syncthreads();
    return r;
}

__global__ void finalize_kernel(const float* __restrict__ nms_reg,
                                const float* __restrict__ bboxes,
                                const int*   __restrict__ classes,
                                const float* __restrict__ anchors,
                                const float* __restrict__ rpn_reg,
                                const float* __restrict__ rpn_cls,
                                float* __restrict__ out) {
    __shared__ float sbuf[512];
    int tid = threadIdx.x;

    float a = 0.f;
    if (tid < 380) {
        int i = (tid < 128) ? g_pos[tid] : g_neg[tid - 128];
        float x = rpn_cls[i];
        float lbl = (tid < 128) ? 1.f : 0.f;
        a = fmaxf(x, 0.f) - x * lbl + log1pf(expf(-fabsf(x)));
    }
    float rpnCls = blockReduceSum512(a, sbuf) / 380.f;

    float bsum = 0.f;
    {
        int jj = tid >> 2, c = tid & 3;
        int i = g_pos[jj];
        int b = i / A_;
        int aidx = i - b * A_;
        float pred = rpn_reg[i*4 + c];
        float tgt = bboxes[(b*T_ + g_tidx[i])*4 + c] - anchors[aidx*4 + c];
        float d = fabsf(pred - tgt);
        bsum = (d < 1.f) ? 0.5f*d*d : d - 0.5f;
    }
    float rpnReg = blockReduceSum512(bsum, sbuf) / 512.f / 4.f;

    float csum = 0.f, accsum = 0.f;
    if (tid < 256) {
        int j = tid;
        int cls = 0;
        if (j < NPOS_) {
            int i = g_posr[j];
            int b = i / R_;
            cls = classes[b*T_ + g_ridx[i]];
        }
        const float* row = &g_rcls[j*NCLS_];
        float mx = row[0];
        #pragma unroll
        for (int c = 1; c < NCLS_; c++) mx = fmaxf(mx, row[c]);
        float se = 0.f;
        #pragma unroll
        for (int c = 0; c < NCLS_; c++) se += expf(row[c] - mx);
        float lse = mx + logf(se);
        csum = lse - row[cls];
        if (j < NPOS_) {
            int am = 0; float bv = row[0];
            #pragma unroll
            for (int c = 1; c < NCLS_; c++) if (row[c] > bv) { bv = row[c]; am = c; }
            accsum = (am == cls) ? 1.f : 0.f;
        }
    }
    float rcnnCls = blockReduceSum512(csum, sbuf) / 256.f;
    float acc     = blockReduceSum512(accsum, sbuf) / (float)NPOS_;

    float dsl = 0.f, dab = 0.f;
    if (tid < NPOS_*4) {
        int jj = tid >> 2, c = tid & 3;
        int i = g_posr[jj];
        int b = i / R_;
        float v = nms_reg[i*4 + c];
        float rounded = (c < 2) ? floorf(v * 16.f) / 16.f : ceilf(v * 16.f) / 16.f;
        float mb = bboxes[(b*T_ + g_ridx[i])*4 + c];
        float tgt = mb - rounded;
        float pr = g_rreg[jj*4 + c];
        float d = fabsf(pr - tgt);
        dsl = (d < 1.f) ? 0.5f*d*d : d - 0.5f;
        dab = d;
    }
    float rcnnReg = blockReduceSum512(dsl, sbuf) / (float)NPOS_ / 4.f;
    float offset  = blockReduceSum512(dab, sbuf) / (float)NPOS_ / 4.f;

    if (tid == 0) {
        out[0] = rpnCls;
        out[1] = rpnReg;
        out[2] = rcnnCls;
        out[3] = rcnnReg;
        out[4] = acc;
        out[5] = offset;
    }
}

// ---------------- launch ----------------
extern "C" void kernel_launch(void* const* d_in, const int* in_sizes, int n_in,
                              void* d_out, int out_size) {
    const float* nms_reg  = (const float*)d_in[0];
    const float* fm       = (const float*)d_in[2];
    const float* bboxes   = (const float*)d_in[3];
    const int*   classes  = (const int*)  d_in[4];
    const float* anchors  = (const float*)d_in[5];
    const float* rpn_reg  = (const float*)d_in[6];
    const float* rpn_cls  = (const float*)d_in[7];
    const float* W1       = (const float*)d_in[8];
    const float* b1       = (const float*)d_in[9];
    const float* Wr       = (const float*)d_in[10];
    const float* br       = (const float*)d_in[11];
    const float* Wc       = (const float*)d_in[12];
    const float* bc       = (const float*)d_in[13];
    float* out = (float*)d_out;

    cudaFuncSetAttribute(gemm_mma_kernel, cudaFuncAttributeMaxDynamicSharedMemorySize, SMEM_GEMM_);

    prep_kernel<<<PB_TOTAL, 256>>>(fm, bboxes, anchors, nms_reg);
    sel_kernel<<<SEL_NBLK_, 1024>>>(nms_reg);
    gemm_mma_kernel<<<dim3(16, 2, KT_), 256, SMEM_GEMM_>>>(W1, b1);
    mlp_tail_kernel<<<256, 1024>>>(Wr, br, Wc, bc);
    finalize_kernel<<<1, 512>>>(nms_reg, bboxes, classes, anchors, rpn_reg, rpn_cls, out);
}

// round 11
// speedup vs baseline: 1.0745x; 1.0745x over previous
#include <cuda_runtime.h>
#include <cuda_bf16.h>
#include <math.h>
#include <stdint.h>

#define B_ 4
#define T_ 40
#define R_ 2000
#define A_ 36864
#define H_ 64
#define W_ 64
#define C_ 256
#define PP_ 7
#define NCLS_ 21
#define NPOS_ 64
#define NNEG_ 192
#define DH_ 1024
#define D_ (PP_*PP_*C_)   // 12544
#define KT_ 8             // split-K factor
#define KPC_ (D_/KT_)     // 1568 per CTA
#define BK_ 32
#define NIT_ (KPC_/BK_)   // 49

// GEMM smem: A tiles bf16 rows padded to 40 elems (80B); B tile fp32 rows padded to 68 words
#define TPAD_ 40
#define ATILE_ (128*TPAD_*2)            // 10240
#define BPADW_ 68
#define BTILEF_ (32*BPADW_*4)           // 8704
#define STAGE_ (2*ATILE_ + BTILEF_)     // 29184
#define NSTG_ 3
#define SMEM_GEMM_ (NSTG_*STAGE_)       // 87552

// ---------------- scratch ----------------
__device__ float g_fmt[B_*H_*W_*C_];
__device__ float g_maxiou[B_*A_];
__device__ int   g_tidx[B_*A_];
__device__ float g_ioum[B_*R_];
__device__ int   g_ridx[B_*R_];
__device__ int   g_pos[128];
__device__ int   g_neg[252];
__device__ int   g_posr[NPOS_];
__device__ int   g_negr[NNEG_];
__device__ int   g_cntP[18], g_cntN[18];
__device__ int   g_cntReady;
__device__ int   g_selDone;
__device__ int   g_tailDone;
__device__ __nv_bfloat16 g_Ahi[256*D_];
__device__ __nv_bfloat16 g_Alo[256*D_];
__device__ float g_partial[KT_][256*DH_];
__device__ float g_rreg[256*4];
__device__ float g_rcls[256*NCLS_];

__device__ __forceinline__ uint32_t smem_u32(const void* p) {
    uint32_t a;
    asm("{ .reg .u64 t; cvta.to.shared.u64 t, %1; cvt.u32.u64 %0, t; }" : "=r"(a) : "l"(p));
    return a;
}
__device__ __forceinline__ unsigned fkey(float f) {
    unsigned u = __float_as_uint(f);
    return (u & 0x80000000u) ? ~u : (u | 0x80000000u);
}

// ---------------- fused prep: init | transpose | rpn_iou | rcnn_iou (R8 exact) ----------------
#define PB_TRANS 4096                   // 2*8*256
#define PB_RPN   576                    // 144*4
#define PB_RCNN  32                     // 8*4
#define PB_TOTAL (PB_TRANS + PB_RPN + PB_RCNN + 1)

__global__ void prep_kernel(const float* __restrict__ fm,
                            const float* __restrict__ bboxes,
                            const float* __restrict__ anchors,
                            const float* __restrict__ nms_reg) {
    __shared__ float tile[32][33];
    int blk = blockIdx.x;
    int tid = threadIdx.x;          // 256
    if (blk < PB_TRANS) {
        int bh = blk >> 4;
        int sub = blk & 15;
        int x0 = (sub & 1) * 32, c0 = (sub >> 1) * 32;
        int b = bh >> 6, y = bh & 63;
        int tx = tid & 31, ty = tid >> 5;
        #pragma unroll
        for (int i = 0; i < 4; i++) {
            int c = c0 + ty + i*8;
            tile[ty + i*8][tx] = fm[((b*C_ + c)*H_ + y)*W_ + x0 + tx];
        }
        __syncthreads();
        #pragma unroll
        for (int i = 0; i < 4; i++) {
            int xr = ty + i*8;
            g_fmt[((b*H_ + y)*W_ + x0+xr)*C_ + c0+tx] = tile[tx][xr];
        }
        return;
    }
    blk -= PB_TRANS;
    if (blk < PB_RPN) {
        int b = blk / 144, bx = blk % 144;
        float* sb = &tile[0][0];
        if (tid < T_*4) sb[tid] = bboxes[b*T_*4 + tid];
        __syncthreads();
        int a = bx*256 + tid;
        float4 an = ((const float4*)anchors)[a];
        float area2 = (an.z-an.x)*(an.w-an.y);
        float best = -1.0f; int bi = 0;
        #pragma unroll 4
        for (int t = 0; t < T_; t++) {
            float bt = sb[t*4+0], bl = sb[t*4+1], bb = sb[t*4+2], br = sb[t*4+3];
            float inter = fmaxf(fminf(bb,an.z)-fmaxf(bt,an.x),0.f)
                        * fmaxf(fminf(br,an.w)-fmaxf(bl,an.y),0.f);
            float a1 = (bb-bt)*(br-bl);
            float iou = inter / (a1 + area2 - inter);
            if (iou > best) { best = iou; bi = t; }
        }
        g_maxiou[b*A_+a] = best;
        g_tidx[b*A_+a] = bi;
        return;
    }
    blk -= PB_RPN;
    if (blk < PB_RCNN) {
        int b = blk >> 3, rx = blk & 7;
        float* sb = &tile[0][0];
        if (tid < T_*4) sb[tid] = bboxes[b*T_*4 + tid];
        __syncthreads();
        int r = rx*256 + tid;
        if (r >= R_) return;
        float4 nr4 = ((const float4*)nms_reg)[b*R_+r];
        float area1 = (nr4.z-nr4.x)*(nr4.w-nr4.y);
        float best = -1.0f; int bi = 0;
        #pragma unroll 4
        for (int t = 0; t < T_; t++) {
            float bt = sb[t*4+0], bl = sb[t*4+1], bb = sb[t*4+2], br = sb[t*4+3];
            float inter = fmaxf(fminf(bb,nr4.z)-fmaxf(bt,nr4.x),0.f)
                        * fmaxf(fminf(br,nr4.w)-fmaxf(bl,nr4.y),0.f);
            float a2 = (bb-bt)*(br-bl);
            float iou = inter / (area1 + a2 - inter);
            if (iou > best) { best = iou; bi = t; }
        }
        g_ioum[b*R_+r] = best;
        g_ridx[b*R_+r] = bi;
        return;
    }
    // init block
    if (tid < 128)  g_pos[tid]  = 0;
    if (tid < 252)  g_neg[tid]  = 0;
    if (tid < NPOS_) g_posr[tid] = 0;
    if (tid == 0) { g_cntReady = 0; g_selDone = 0; g_tailDone = 0; }
}

// ============ fused selection: rpn(blocks 0-17) | topk+posr(18) | roi(19-82) (R8 exact) ============
#define SEL_RPN_ 18
#define SEL_TOPK_ 18
#define SEL_ROI0_ 19
#define SEL_NBLK_ 83

__global__ void __launch_bounds__(1024, 2) sel_kernel(const float* __restrict__ nms_reg) {
    __shared__ float sv[B_*R_];
    __shared__ int hist[256];
    __shared__ int sS[256];
    __shared__ int sCnt[32], sOff[32], sCnt2[32], sOff2[32];
    __shared__ int sTot, sTot2;
    __shared__ unsigned sPrefix;
    __shared__ int sRemain, sCntG;
    __shared__ int sBaseP, sBaseN;

    int blk = blockIdx.x;
    int tid = threadIdx.x, lane = tid & 31, wid = tid >> 5;

    if (blk < SEL_RPN_) {
        int c = blk;
        int cp = 0;
        float v8[8];
        #pragma unroll
        for (int i = 0; i < 8; i++) {
            v8[i] = g_maxiou[c*8192 + i*1024 + tid];
            cp += (v8[i] > 0.5f) ? 1 : 0;
        }
        #pragma unroll
        for (int d = 16; d; d >>= 1) cp += __shfl_down_sync(0xffffffffu, cp, d);
        if (lane == 0) sCnt[wid] = cp;
        __syncthreads();
        if (wid == 0) {
            int s = sCnt[lane];
            #pragma unroll
            for (int d = 16; d; d >>= 1) s += __shfl_down_sync(0xffffffffu, s, d);
            if (lane == 0) {
                g_cntP[c] = s; g_cntN[c] = 8192 - s;
                __threadfence();
                atomicAdd(&g_cntReady, 1);
            }
        }
        if (tid == 0) {
            while (atomicAdd(&g_cntReady, 0) < 18) {}
            int bp = 0, bn = 0;
            for (int i = 0; i < c; i++) { bp += g_cntP[i]; bn += g_cntN[i]; }
            sBaseP = bp; sBaseN = bn;
        }
        __syncthreads();
        int baseP = sBaseP, baseN = sBaseN;
        if (baseP >= 128 && baseN >= 252) return;
        for (int ph = 0; ph < 8; ph++) {
            int j = c*8192 + ph*1024 + tid;
            bool fp = (v8[ph] > 0.5f), fn = !fp;
            unsigned mp = __ballot_sync(0xffffffffu, fp);
            unsigned mn = __ballot_sync(0xffffffffu, fn);
            if (lane == 0) { sCnt[wid] = __popc(mp); sCnt2[wid] = __popc(mn); }
            __syncthreads();
            if (wid == 0) {
                int cp2 = sCnt[lane], cn2 = sCnt2[lane];
                int sp = cp2, sn = cn2;
                #pragma unroll
                for (int d = 1; d < 32; d <<= 1) {
                    int tp = __shfl_up_sync(0xffffffffu, sp, d);
                    int tn = __shfl_up_sync(0xffffffffu, sn, d);
                    if (lane >= d) { sp += tp; sn += tn; }
                }
                sOff[lane] = sp - cp2; sOff2[lane] = sn - cn2;
                if (lane == 31) { sTot = sp; sTot2 = sn; }
            }
            __syncthreads();
            if (fp) {
                int p = baseP + sOff[wid] + __popc(mp & ((1u << lane) - 1u));
                if (p < 128) g_pos[p] = j;
            }
            if (fn) {
                int p = baseN + sOff2[wid] + __popc(mn & ((1u << lane) - 1u));
                if (p < 252) g_neg[p] = j;
            }
            baseP += sTot; baseN += sTot2;
            __syncthreads();
            if (baseP >= 128 && baseN >= 252) return;
        }
        return;
    }

    if (blk == SEL_TOPK_) {
        for (int j = tid; j < B_*R_; j += 1024) {
            float v = g_ioum[j];
            sv[j] = (v <= 0.5f) ? v : -INFINITY;
        }
        if (tid == 0) { sPrefix = 0; sRemain = NNEG_; sCntG = 0; }
        __syncthreads();

        int base = 0;
        for (int ph = 0; ph < 8 && base < NPOS_; ph++) {
            int j = ph*1024 + tid;
            bool f = (j < B_*R_) && (g_ioum[j] > 0.5f);
            unsigned m = __ballot_sync(0xffffffffu, f);
            if (lane == 0) sCnt[wid] = __popc(m);
            __syncthreads();
            if (wid == 0) {
                int cp = sCnt[lane], sp = cp;
                #pragma unroll
                for (int d = 1; d < 32; d <<= 1) {
                    int tp = __shfl_up_sync(0xffffffffu, sp, d);
                    if (lane >= d) sp += tp;
                }
                sOff[lane] = sp - cp;
                if (lane == 31) sTot = sp;
            }
            __syncthreads();
            if (f) {
                int p = base + sOff[wid] + __popc(m & ((1u << lane) - 1u));
                if (p < NPOS_) g_posr[p] = j;
            }
            base += sTot;
            __syncthreads();
        }

        for (int lvl = 24; lvl >= 0; lvl -= 8) {
            if (tid < 256) hist[tid] = 0;
            __syncthreads();
            unsigned pfx = sPrefix;
            int need = sRemain;
            for (int j = tid; j < B_*R_; j += 1024) {
                unsigned k = fkey(sv[j]);
                bool match = (lvl == 24) || ((k >> (lvl+8)) == pfx);
                if (match) atomicAdd(&hist[(k >> lvl) & 255], 1);
            }
            __syncthreads();
            if (tid < 256) sS[tid] = hist[tid];
            __syncthreads();
            #pragma unroll
            for (int d = 1; d < 256; d <<= 1) {
                int v = 0;
                if (tid < 256 && tid + d < 256) v = sS[tid + d];
                __syncthreads();
                if (tid < 256) sS[tid] += v;
                __syncthreads();
            }
            if (tid < 256) {
                int Sb = sS[tid];
                int Snext = (tid < 255) ? sS[tid+1] : 0;
                if (Sb >= need && Snext < need) {
                    sPrefix = (pfx << 8) | (unsigned)tid;
                    sRemain = need - Snext;
                }
            }
            __syncthreads();
        }
        unsigned K = sPrefix;
        int needEq = sRemain;
        int G = NNEG_ - needEq;

        for (int j = tid; j < B_*R_; j += 1024) {
            if (fkey(sv[j]) > K) {
                int p = atomicAdd(&sCntG, 1);
                g_negr[p] = j;
            }
        }
        __syncthreads();
        base = 0;
        for (int ph = 0; ph < 8 && base < needEq; ph++) {
            int j = ph*1024 + tid;
            bool f = (j < B_*R_) && (fkey(sv[j]) == K);
            unsigned m = __ballot_sync(0xffffffffu, f);
            if (lane == 0) sCnt[wid] = __popc(m);
            __syncthreads();
            if (wid == 0) {
                int cp = sCnt[lane], sp = cp;
                #pragma unroll
                for (int d = 1; d < 32; d <<= 1) {
                    int tp = __shfl_up_sync(0xffffffffu, sp, d);
                    if (lane >= d) sp += tp;
                }
                sOff[lane] = sp - cp;
                if (lane == 31) sTot = sp;
            }
            __syncthreads();
            if (f) {
                int p = base + sOff[wid] + __popc(m & ((1u << lane) - 1u));
                if (p < needEq) g_negr[G + p] = j;
            }
            base += sTot;
            __syncthreads();
        }
        __syncthreads();
        if (tid == 0) {
            __threadfence();
            atomicExch(&g_selDone, 1);
        }
        return;
    }

    // ---- ROI pool: 4 rois per block, spin on topk done ----
    if (tid == 0) {
        while (atomicAdd(&g_selDone, 0) == 0) {}
    }
    __syncthreads();
    int j = (blk - SEL_ROI0_) * 4 + (tid >> 8);
    int c = tid & 255;
    int sel = (j < NPOS_) ? g_posr[j] : g_negr[j - NPOS_];
    int b = sel / R_;
    float t  = nms_reg[sel*4+0], l = nms_reg[sel*4+1];
    float bb = nms_reg[sel*4+2], r = nms_reg[sel*4+3];
    const float* fb = g_fmt + (size_t)b * H_ * W_ * C_;
    for (int p = 0; p < PP_*PP_; p++) {
        int py = p / PP_, px = p % PP_;
        float gy = (py + 0.5f) / (float)PP_;
        float gx = (px + 0.5f) / (float)PP_;
        float y = fminf(fmaxf(t + gy * (bb - t), 0.f), (float)(H_-1));
        float x = fminf(fmaxf(l + gx * (r  - l), 0.f), (float)(W_-1));
        int y0 = (int)floorf(y), x0 = (int)floorf(x);
        int y1 = min(y0 + 1, H_-1), x1 = min(x0 + 1, W_-1);
        float wy = y - (float)y0, wx = x - (float)x0;
        float v00 = fb[(y0*W_+x0)*C_ + c];
        float v01 = fb[(y0*W_+x1)*C_ + c];
        float v10 = fb[(y1*W_+x0)*C_ + c];
        float v11 = fb[(y1*W_+x1)*C_ + c];
        float v = v00*(1.f-wy)*(1.f-wx) + v01*(1.f-wy)*wx
                + v10*wy*(1.f-wx)       + v11*wy*wx;
        __nv_bfloat16 h = __float2bfloat16(v);
        int o = j*D_ + p*C_ + c;
        g_Ahi[o] = h;
        g_Alo[o] = __float2bfloat16(v - __bfloat162float(h));
    }
}

// ---------------- mma.sync GEMM: BM128 BN64 BK32, 3-stage, split-K=8 ----------------
// warp tile 64x16 (evidence: R9 vs R10 = -4.5us); R8's plain partial-write epilogue.
__device__ __forceinline__ void ldsm_x4(uint32_t* r, uint32_t addr) {
    asm volatile("ldmatrix.sync.aligned.m8n8.x4.shared.b16 {%0,%1,%2,%3}, [%4];"
        : "=r"(r[0]), "=r"(r[1]), "=r"(r[2]), "=r"(r[3]) : "r"(addr));
}
__device__ __forceinline__ void mma16816(float* d, const uint32_t* a, const uint32_t* b) {
    asm volatile("mma.sync.aligned.m16n8k16.row.col.f32.bf16.bf16.f32 "
        "{%0,%1,%2,%3}, {%4,%5,%6,%7}, {%8,%9}, {%0,%1,%2,%3};"
        : "+f"(d[0]), "+f"(d[1]), "+f"(d[2]), "+f"(d[3])
        : "r"(a[0]), "r"(a[1]), "r"(a[2]), "r"(a[3]), "r"(b[0]), "r"(b[1]));
}
__device__ __forceinline__ void cp16(uint32_t saddr, const void* gaddr) {
    asm volatile("cp.async.cg.shared.global [%0], [%1], 16;" :: "r"(saddr), "l"(gaddr));
}

__global__ void __launch_bounds__(256, 2) gemm_mma_kernel(const float* __restrict__ W1) {
    extern __shared__ char smem[];
    uint32_t sb = smem_u32(smem);
    int tid = threadIdx.x, wid = tid >> 5, lane = tid & 31;
    int n0 = blockIdx.x * 64;
    int m0 = blockIdx.y * 128;
    int kt = blockIdx.z;
    int kbase = kt * KPC_;
    int wm = wid >> 2, wn = wid & 3;     // warp tile 64x16

    const uint4* bAhi = (const uint4*)g_Ahi + (size_t)m0 * (D_/8);
    const uint4* bAlo = (const uint4*)g_Alo + (size_t)m0 * (D_/8);

    int a0r = tid >> 2,          a0q = tid & 3;
    int a1r = (tid + 256) >> 2,  a1q = tid & 3;
    int b0r = tid >> 4, b0q = tid & 15;

    auto load_stage = [&](int it) {
        uint32_t sg = sb + (it % NSTG_) * STAGE_;
        int kk = kbase + it*BK_;
        int kq = kk >> 3;
        cp16(sg +          a0r*80 + a0q*16, bAhi + (size_t)a0r*(D_/8) + kq + a0q);
        cp16(sg +          a1r*80 + a1q*16, bAhi + (size_t)a1r*(D_/8) + kq + a1q);
        cp16(sg + ATILE_ + a0r*80 + a0q*16, bAlo + (size_t)a0r*(D_/8) + kq + a0q);
        cp16(sg + ATILE_ + a1r*80 + a1q*16, bAlo + (size_t)a1r*(D_/8) + kq + a1q);
        uint32_t bg = sg + 2*ATILE_;
        cp16(bg + b0r*(BPADW_*4) + b0q*16,      W1 + (size_t)(kk + b0r)*DH_ + n0 + b0q*4);
        cp16(bg + (b0r+16)*(BPADW_*4) + b0q*16, W1 + (size_t)(kk + b0r+16)*DH_ + n0 + b0q*4);
        asm volatile("cp.async.commit_group;");
    };

    float acc[4][2][4];
    #pragma unroll
    for (int i = 0; i < 4; i++)
        #pragma unroll
        for (int j = 0; j < 2; j++)
            #pragma unroll
            for (int q = 0; q < 4; q++) acc[i][j][q] = 0.f;

    load_stage(0);
    load_stage(1);

    for (int it = 0; it < NIT_; it++) {
        asm volatile("cp.async.wait_group 1;");
        __syncthreads();
        if (it + 2 < NIT_) load_stage(it + 2);
        else asm volatile("cp.async.commit_group;");

        uint32_t sg = sb + (it % NSTG_) * STAGE_;
        uint32_t aHiB = sg, aLoB = sg + ATILE_;
        const float* sBf = (const float*)(smem + (it % NSTG_) * STAGE_ + 2*ATILE_);

        #pragma unroll
        for (int ks = 0; ks < 2; ks++) {
            int acol = ks*16 + ((lane >> 4) & 1) * 8;
            uint32_t ahi[4][4], alo[4][4], bhi[2][2], blo[2][2];
            #pragma unroll
            for (int mt = 0; mt < 4; mt++) {
                int arow = wm*64 + mt*16 + (lane & 15);
                uint32_t off = arow*80 + acol*2;
                ldsm_x4(ahi[mt], aHiB + off);
                ldsm_x4(alo[mt], aLoB + off);
            }
            #pragma unroll
            for (int nt = 0; nt < 2; nt++) {
                int nn = wn*16 + nt*8 + (lane >> 2);
                #pragma unroll
                for (int rg = 0; rg < 2; rg++) {
                    int kk2 = ks*16 + (lane & 3)*2 + rg*8;
                    float v0 = sBf[(kk2+0)*BPADW_ + nn];
                    float v1 = sBf[(kk2+1)*BPADW_ + nn];
                    uint32_t hreg;
                    asm("cvt.rn.bf16x2.f32 %0, %1, %2;" : "=r"(hreg) : "f"(v1), "f"(v0));
                    float h0 = __uint_as_float(hreg << 16);
                    float h1 = __uint_as_float(hreg & 0xFFFF0000u);
                    uint32_t lreg;
                    asm("cvt.rn.bf16x2.f32 %0, %1, %2;" : "=r"(lreg) : "f"(v1-h1), "f"(v0-h0));
                    bhi[nt][rg] = hreg;
                    blo[nt][rg] = lreg;
                }
            }
            #pragma unroll
            for (int mt = 0; mt < 4; mt++)
                #pragma unroll
                for (int nt = 0; nt < 2; nt++) {
                    mma16816(acc[mt][nt], ahi[mt], bhi[nt]);
                    mma16816(acc[mt][nt], ahi[mt], blo[nt]);
                    mma16816(acc[mt][nt], alo[mt], bhi[nt]);
                }
        }
    }

    // write split-K partials (plain, no fences)
    float* outp = g_partial[kt];
    int g = lane >> 2, qc = (lane & 3) * 2;
    #pragma unroll
    for (int mt = 0; mt < 4; mt++) {
        #pragma unroll
        for (int nt = 0; nt < 2; nt++) {
            int row = m0 + wm*64 + mt*16 + g;
            int col = n0 + wn*16 + nt*8 + qc;
            *(float2*)&outp[(size_t)row*DH_ + col]     = make_float2(acc[mt][nt][0], acc[mt][nt][1]);
            *(float2*)&outp[(size_t)(row+8)*DH_ + col] = make_float2(acc[mt][nt][2], acc[mt][nt][3]);
        }
    }
}

// ---------------- merged tail: reduce+bias+relu+heads (blocks 0-255) | finalize (block 256) ----------------
__global__ void __launch_bounds__(1024, 2) tail_kernel(
        const float* __restrict__ b1,
        const float* __restrict__ Wr, const float* __restrict__ br,
        const float* __restrict__ Wc, const float* __restrict__ bc,
        const float* __restrict__ nms_reg,
        const float* __restrict__ bboxes,
        const int*   __restrict__ classes,
        const float* __restrict__ anchors,
        const float* __restrict__ rpn_reg,
        const float* __restrict__ rpn_cls,
        float* __restrict__ out) {
    int tid = threadIdx.x;
    int blk = blockIdx.x;

    if (blk < 256) {
        // ---- per-row: reduce 8 partials + bias + relu -> heads ----
        __shared__ float h[DH_];
        int row = blk;
        float s = b1[tid];
        #pragma unroll
        for (int k = 0; k < KT_; k++)
            s += g_partial[k][(size_t)row*DH_ + tid];
        h[tid] = fmaxf(s, 0.f);
        __syncthreads();
        int wid = tid >> 5, lane = tid & 31;
        if (wid < 4 + NCLS_) {
            float sum = 0.f;
            if (wid < 4) {
                #pragma unroll 8
                for (int k = lane; k < DH_; k += 32) sum += h[k] * Wr[k*4 + wid];
            } else {
                int oc = wid - 4;
                #pragma unroll 8
                for (int k = lane; k < DH_; k += 32) sum += h[k] * Wc[k*NCLS_ + oc];
            }
            #pragma unroll
            for (int d = 16; d; d >>= 1) sum += __shfl_down_sync(0xffffffffu, sum, d);
            if (lane == 0) {
                if (wid < 4) g_rreg[row*4 + wid] = sum + br[wid];
                else         g_rcls[row*NCLS_ + (wid-4)] = sum + bc[wid-4];
            }
        }
        __syncthreads();
        if (tid == 0) {
            __threadfence();
            atomicAdd(&g_tailDone, 1);
        }
        return;
    }

    // ---- finalize block: wait for all 256 rows ----
    __shared__ float sbuf[1024];
    if (tid == 0) {
        while (atomicAdd(&g_tailDone, 0) < 256) {}
    }
    __syncthreads();
    __threadfence();

    auto reduceAll = [&](float v) -> float {
        sbuf[tid] = v; __syncthreads();
        for (int s2 = 512; s2 > 0; s2 >>= 1) {
            if (tid < s2) sbuf[tid] += sbuf[tid + s2];
            __syncthreads();
        }
        float r = sbuf[0]; __syncthreads();
        return r;
    };

    float a = 0.f;
    if (tid < 380) {
        int i = (tid < 128) ? g_pos[tid] : g_neg[tid - 128];
        float x = rpn_cls[i];
        float lbl = (tid < 128) ? 1.f : 0.f;
        a = fmaxf(x, 0.f) - x * lbl + log1pf(expf(-fabsf(x)));
    }
    float rpnCls = reduceAll(a) / 380.f;

    float bsum = 0.f;
    if (tid < 512) {
        int jj = tid >> 2, c = tid & 3;
        int i = g_pos[jj];
        int b = i / A_;
        int aidx = i - b * A_;
        float pred = rpn_reg[i*4 + c];
        float tgt = bboxes[(b*T_ + g_tidx[i])*4 + c] - anchors[aidx*4 + c];
        float d = fabsf(pred - tgt);
        bsum = (d < 1.f) ? 0.5f*d*d : d - 0.5f;
    }
    float rpnReg = reduceAll(bsum) / 512.f / 4.f;

    float csum = 0.f, accsum = 0.f;
    if (tid < 256) {
        int j = tid;
        int cls = 0;
        if (j < NPOS_) {
            int i = g_posr[j];
            int b = i / R_;
            cls = classes[b*T_ + g_ridx[i]];
        }
        const float* row = &g_rcls[j*NCLS_];
        float mx = row[0];
        #pragma unroll
        for (int c = 1; c < NCLS_; c++) mx = fmaxf(mx, row[c]);
        float se = 0.f;
        #pragma unroll
        for (int c = 0; c < NCLS_; c++) se += expf(row[c] - mx);
        float lse = mx + logf(se);
        csum = lse - row[cls];
        if (j < NPOS_) {
            int am = 0; float bv = row[0];
            #pragma unroll
            for (int c = 1; c < NCLS_; c++) if (row[c] > bv) { bv = row[c]; am = c; }
            accsum = (am == cls) ? 1.f : 0.f;
        }
    }
    float rcnnCls = reduceAll(csum) / 256.f;
    float acc     = reduceAll(accsum) / (float)NPOS_;

    float dsl = 0.f, dab = 0.f;
    if (tid < NPOS_*4) {
        int jj = tid >> 2, c = tid & 3;
        int i = g_posr[jj];
        int b = i / R_;
        float v = nms_reg[i*4 + c];
        float rounded = (c < 2) ? floorf(v * 16.f) / 16.f : ceilf(v * 16.f) / 16.f;
        float mb = bboxes[(b*T_ + g_ridx[i])*4 + c];
        float tgt = mb - rounded;
        float pr = g_rreg[jj*4 + c];
        float d = fabsf(pr - tgt);
        dsl = (d < 1.f) ? 0.5f*d*d : d - 0.5f;
        dab = d;
    }
    float rcnnReg = reduceAll(dsl) / (float)NPOS_ / 4.f;
    float offset  = reduceAll(dab) / (float)NPOS_ / 4.f;

    if (tid == 0) {
        out[0] = rpnCls;
        out[1] = rpnReg;
        out[2] = rcnnCls;
        out[3] = rcnnReg;
        out[4] = acc;
        out[5] = offset;
    }
}

// ---------------- launch ----------------
extern "C" void kernel_launch(void* const* d_in, const int* in_sizes, int n_in,
                              void* d_out, int out_size) {
    const float* nms_reg  = (const float*)d_in[0];
    const float* fm       = (const float*)d_in[2];
    const float* bboxes   = (const float*)d_in[3];
    const int*   classes  = (const int*)  d_in[4];
    const float* anchors  = (const float*)d_in[5];
    const float* rpn_reg  = (const float*)d_in[6];
    const float* rpn_cls  = (const float*)d_in[7];
    const float* W1       = (const float*)d_in[8];
    const float* b1       = (const float*)d_in[9];
    const float* Wr       = (const float*)d_in[10];
    const float* br       = (const float*)d_in[11];
    const float* Wc       = (const float*)d_in[12];
    const float* bc       = (const float*)d_in[13];
    float* out = (float*)d_out;

    cudaFuncSetAttribute(gemm_mma_kernel, cudaFuncAttributeMaxDynamicSharedMemorySize, SMEM_GEMM_);

    prep_kernel<<<PB_TOTAL, 256>>>(fm, bboxes, anchors, nms_reg);
    sel_kernel<<<SEL_NBLK_, 1024>>>(nms_reg);
    gemm_mma_kernel<<<dim3(16, 2, KT_), 256, SMEM_GEMM_>>>(W1);
    tail_kernel<<<257, 1024>>>(b1, Wr, br, Wc, bc,
                               nms_reg, bboxes, classes, anchors, rpn_reg, rpn_cls, out);
}

// round 12
// speedup vs baseline: 1.1178x; 1.0403x over previous
#include <cuda_runtime.h>
#include <cuda_bf16.h>
#include <math.h>
#include <stdint.h>

#define B_ 4
#define T_ 40
#define R_ 2000
#define A_ 36864
#define H_ 64
#define W_ 64
#define C_ 256
#define PP_ 7
#define NCLS_ 21
#define NPOS_ 64
#define NNEG_ 192
#define DH_ 1024
#define D_ (PP_*PP_*C_)   // 12544
#define KT_ 8             // split-K factor
#define KPC_ (D_/KT_)     // 1568 per CTA
#define BK_ 32
#define NIT_ (KPC_/BK_)   // 49

// GEMM smem: A tiles bf16 rows padded to 40 elems (80B); B tile fp32 rows padded to 68 words
#define TPAD_ 40
#define ATILE_ (128*TPAD_*2)            // 10240
#define BPADW_ 68
#define BTILEF_ (32*BPADW_*4)           // 8704
#define STAGE_ (2*ATILE_ + BTILEF_)     // 29184
#define NSTG_ 3
#define SMEM_GEMM_ (NSTG_*STAGE_)       // 87552

// ---------------- scratch ----------------
__device__ float g_fmt[B_*H_*W_*C_];
__device__ float g_maxiou[B_*A_];
__device__ int   g_tidx[B_*A_];
__device__ float g_ioum[B_*R_];
__device__ int   g_ridx[B_*R_];
__device__ int   g_pos[128];
__device__ int   g_neg[252];
__device__ int   g_posr[NPOS_];
__device__ int   g_negr[NNEG_];
__device__ int   g_cntP[18], g_cntN[18];
__device__ int   g_cntReady;
__device__ int   g_selDone;
__device__ float g_WrT[4*DH_];
__device__ float g_WcT[NCLS_*DH_];
__device__ __nv_bfloat16 g_Ahi[256*D_];
__device__ __nv_bfloat16 g_Alo[256*D_];
__device__ float g_partial[KT_][256*DH_];
__device__ float g_rreg[256*4];
__device__ float g_rcls[256*NCLS_];

__device__ __forceinline__ uint32_t smem_u32(const void* p) {
    uint32_t a;
    asm("{ .reg .u64 t; cvta.to.shared.u64 t, %1; cvt.u32.u64 %0, t; }" : "=r"(a) : "l"(p));
    return a;
}
__device__ __forceinline__ unsigned fkey(float f) {
    unsigned u = __float_as_uint(f);
    return (u & 0x80000000u) ? ~u : (u | 0x80000000u);
}

// ---------------- fused prep: transpose | rpn_iou | rcnn_iou | headsT | init ----------------
#define PB_TRANS 4096                   // 2*8*256
#define PB_RPN   576                    // 144*4
#define PB_RCNN  32                     // 8*4
#define PB_HT    100                    // 25*4 blocks: transpose Wr/Wc
#define PB_TOTAL (PB_TRANS + PB_RPN + PB_RCNN + PB_HT + 1)

__global__ void prep_kernel(const float* __restrict__ fm,
                            const float* __restrict__ bboxes,
                            const float* __restrict__ anchors,
                            const float* __restrict__ nms_reg,
                            const float* __restrict__ Wr,
                            const float* __restrict__ Wc) {
    __shared__ float tile[32][33];
    int blk = blockIdx.x;
    int tid = threadIdx.x;          // 256
    if (blk < PB_TRANS) {
        int bh = blk >> 4;
        int sub = blk & 15;
        int x0 = (sub & 1) * 32, c0 = (sub >> 1) * 32;
        int b = bh >> 6, y = bh & 63;
        int tx = tid & 31, ty = tid >> 5;
        #pragma unroll
        for (int i = 0; i < 4; i++) {
            int c = c0 + ty + i*8;
            tile[ty + i*8][tx] = fm[((b*C_ + c)*H_ + y)*W_ + x0 + tx];
        }
        __syncthreads();
        #pragma unroll
        for (int i = 0; i < 4; i++) {
            int xr = ty + i*8;
            g_fmt[((b*H_ + y)*W_ + x0+xr)*C_ + c0+tx] = tile[tx][xr];
        }
        return;
    }
    blk -= PB_TRANS;
    if (blk < PB_RPN) {
        int b = blk / 144, bx = blk % 144;
        float* sb = &tile[0][0];
        if (tid < T_*4) sb[tid] = bboxes[b*T_*4 + tid];
        __syncthreads();
        int a = bx*256 + tid;
        float4 an = ((const float4*)anchors)[a];
        float area2 = (an.z-an.x)*(an.w-an.y);
        float best = -1.0f; int bi = 0;
        #pragma unroll 4
        for (int t = 0; t < T_; t++) {
            float bt = sb[t*4+0], bl = sb[t*4+1], bb = sb[t*4+2], br = sb[t*4+3];
            float inter = fmaxf(fminf(bb,an.z)-fmaxf(bt,an.x),0.f)
                        * fmaxf(fminf(br,an.w)-fmaxf(bl,an.y),0.f);
            float a1 = (bb-bt)*(br-bl);
            float iou = inter / (a1 + area2 - inter);
            if (iou > best) { best = iou; bi = t; }
        }
        g_maxiou[b*A_+a] = best;
        g_tidx[b*A_+a] = bi;
        return;
    }
    blk -= PB_RPN;
    if (blk < PB_RCNN) {
        int b = blk >> 3, rx = blk & 7;
        float* sb = &tile[0][0];
        if (tid < T_*4) sb[tid] = bboxes[b*T_*4 + tid];
        __syncthreads();
        int r = rx*256 + tid;
        if (r >= R_) return;
        float4 nr4 = ((const float4*)nms_reg)[b*R_+r];
        float area1 = (nr4.z-nr4.x)*(nr4.w-nr4.y);
        float best = -1.0f; int bi = 0;
        #pragma unroll 4
        for (int t = 0; t < T_; t++) {
            float bt = sb[t*4+0], bl = sb[t*4+1], bb = sb[t*4+2], br = sb[t*4+3];
            float inter = fmaxf(fminf(bb,nr4.z)-fmaxf(bt,nr4.x),0.f)
                        * fmaxf(fminf(br,nr4.w)-fmaxf(bl,nr4.y),0.f);
            float a2 = (bb-bt)*(br-bl);
            float iou = inter / (area1 + a2 - inter);
            if (iou > best) { best = iou; bi = t; }
        }
        g_ioum[b*R_+r] = best;
        g_ridx[b*R_+r] = bi;
        return;
    }
    blk -= PB_RCNN;
    if (blk < PB_HT) {
        // transpose head weights: each block handles one output o (of 25) x 256-k slice
        int o = blk / 4, kq = blk % 4;
        int k = kq*256 + tid;
        if (o < 4) g_WrT[o*DH_ + k] = Wr[k*4 + o];
        else       g_WcT[(o-4)*DH_ + k] = Wc[k*NCLS_ + (o-4)];
        return;
    }
    // init block
    if (tid < 128)  g_pos[tid]  = 0;
    if (tid < 252)  g_neg[tid]  = 0;
    if (tid < NPOS_) g_posr[tid] = 0;
    if (tid == 0) { g_cntReady = 0; g_selDone = 0; }
}

// ============ fused selection: rpn(blocks 0-17) | topk+posr(18) | roi(19-82) ============
#define SEL_RPN_ 18
#define SEL_TOPK_ 18
#define SEL_ROI0_ 19
#define SEL_NBLK_ 83

__global__ void __launch_bounds__(1024, 2) sel_kernel(const float* __restrict__ nms_reg) {
    __shared__ float sv[B_*R_];
    __shared__ int hist[256];
    __shared__ int sS[256];
    __shared__ int sCnt[32], sOff[32], sCnt2[32], sOff2[32];
    __shared__ int sTot, sTot2;
    __shared__ unsigned sPrefix;
    __shared__ int sRemain, sCntG;
    __shared__ int sBaseP, sBaseN;

    int blk = blockIdx.x;
    int tid = threadIdx.x, lane = tid & 31, wid = tid >> 5;

    if (blk < SEL_RPN_) {
        int c = blk;
        int cp = 0;
        float v8[8];
        #pragma unroll
        for (int i = 0; i < 8; i++) {
            v8[i] = g_maxiou[c*8192 + i*1024 + tid];
            cp += (v8[i] > 0.5f) ? 1 : 0;
        }
        #pragma unroll
        for (int d = 16; d; d >>= 1) cp += __shfl_down_sync(0xffffffffu, cp, d);
        if (lane == 0) sCnt[wid] = cp;
        __syncthreads();
        if (wid == 0) {
            int s = sCnt[lane];
            #pragma unroll
            for (int d = 16; d; d >>= 1) s += __shfl_down_sync(0xffffffffu, s, d);
            if (lane == 0) {
                g_cntP[c] = s; g_cntN[c] = 8192 - s;
                __threadfence();
                atomicAdd(&g_cntReady, 1);
            }
        }
        if (tid == 0) {
            while (atomicAdd(&g_cntReady, 0) < 18) {}
            int bp = 0, bn = 0;
            for (int i = 0; i < c; i++) { bp += g_cntP[i]; bn += g_cntN[i]; }
            sBaseP = bp; sBaseN = bn;
        }
        __syncthreads();
        int baseP = sBaseP, baseN = sBaseN;
        if (baseP >= 128 && baseN >= 252) return;
        for (int ph = 0; ph < 8; ph++) {
            int j = c*8192 + ph*1024 + tid;
            bool fp = (v8[ph] > 0.5f), fn = !fp;
            unsigned mp = __ballot_sync(0xffffffffu, fp);
            unsigned mn = __ballot_sync(0xffffffffu, fn);
            if (lane == 0) { sCnt[wid] = __popc(mp); sCnt2[wid] = __popc(mn); }
            __syncthreads();
            if (wid == 0) {
                int cp2 = sCnt[lane], cn2 = sCnt2[lane];
                int sp = cp2, sn = cn2;
                #pragma unroll
                for (int d = 1; d < 32; d <<= 1) {
                    int tp = __shfl_up_sync(0xffffffffu, sp, d);
                    int tn = __shfl_up_sync(0xffffffffu, sn, d);
                    if (lane >= d) { sp += tp; sn += tn; }
                }
                sOff[lane] = sp - cp2; sOff2[lane] = sn - cn2;
                if (lane == 31) { sTot = sp; sTot2 = sn; }
            }
            __syncthreads();
            if (fp) {
                int p = baseP + sOff[wid] + __popc(mp & ((1u << lane) - 1u));
                if (p < 128) g_pos[p] = j;
            }
            if (fn) {
                int p = baseN + sOff2[wid] + __popc(mn & ((1u << lane) - 1u));
                if (p < 252) g_neg[p] = j;
            }
            baseP += sTot; baseN += sTot2;
            __syncthreads();
            if (baseP >= 128 && baseN >= 252) return;
        }
        return;
    }

    if (blk == SEL_TOPK_) {
        for (int j = tid; j < B_*R_; j += 1024) {
            float v = g_ioum[j];
            sv[j] = (v <= 0.5f) ? v : -INFINITY;
        }
        if (tid == 0) { sPrefix = 0; sRemain = NNEG_; sCntG = 0; }
        __syncthreads();

        int base = 0;
        for (int ph = 0; ph < 8 && base < NPOS_; ph++) {
            int j = ph*1024 + tid;
            bool f = (j < B_*R_) && (g_ioum[j] > 0.5f);
            unsigned m = __ballot_sync(0xffffffffu, f);
            if (lane == 0) sCnt[wid] = __popc(m);
            __syncthreads();
            if (wid == 0) {
                int cp = sCnt[lane], sp = cp;
                #pragma unroll
                for (int d = 1; d < 32; d <<= 1) {
                    int tp = __shfl_up_sync(0xffffffffu, sp, d);
                    if (lane >= d) sp += tp;
                }
                sOff[lane] = sp - cp;
                if (lane == 31) sTot = sp;
            }
            __syncthreads();
            if (f) {
                int p = base + sOff[wid] + __popc(m & ((1u << lane) - 1u));
                if (p < NPOS_) g_posr[p] = j;
            }
            base += sTot;
            __syncthreads();
        }

        for (int lvl = 24; lvl >= 0; lvl -= 8) {
            if (tid < 256) hist[tid] = 0;
            __syncthreads();
            unsigned pfx = sPrefix;
            int need = sRemain;
            for (int j = tid; j < B_*R_; j += 1024) {
                unsigned k = fkey(sv[j]);
                bool match = (lvl == 24) || ((k >> (lvl+8)) == pfx);
                if (match) atomicAdd(&hist[(k >> lvl) & 255], 1);
            }
            __syncthreads();
            if (tid < 256) sS[tid] = hist[tid];
            __syncthreads();
            #pragma unroll
            for (int d = 1; d < 256; d <<= 1) {
                int v = 0;
                if (tid < 256 && tid + d < 256) v = sS[tid + d];
                __syncthreads();
                if (tid < 256) sS[tid] += v;
                __syncthreads();
            }
            if (tid < 256) {
                int Sb = sS[tid];
                int Snext = (tid < 255) ? sS[tid+1] : 0;
                if (Sb >= need && Snext < need) {
                    sPrefix = (pfx << 8) | (unsigned)tid;
                    sRemain = need - Snext;
                }
            }
            __syncthreads();
        }
        unsigned K = sPrefix;
        int needEq = sRemain;
        int G = NNEG_ - needEq;

        for (int j = tid; j < B_*R_; j += 1024) {
            if (fkey(sv[j]) > K) {
                int p = atomicAdd(&sCntG, 1);
                g_negr[p] = j;
            }
        }
        __syncthreads();
        base = 0;
        for (int ph = 0; ph < 8 && base < needEq; ph++) {
            int j = ph*1024 + tid;
            bool f = (j < B_*R_) && (fkey(sv[j]) == K);
            unsigned m = __ballot_sync(0xffffffffu, f);
            if (lane == 0) sCnt[wid] = __popc(m);
            __syncthreads();
            if (wid == 0) {
                int cp = sCnt[lane], sp = cp;
                #pragma unroll
                for (int d = 1; d < 32; d <<= 1) {
                    int tp = __shfl_up_sync(0xffffffffu, sp, d);
                    if (lane >= d) sp += tp;
                }
                sOff[lane] = sp - cp;
                if (lane == 31) sTot = sp;
            }
            __syncthreads();
            if (f) {
                int p = base + sOff[wid] + __popc(m & ((1u << lane) - 1u));
                if (p < needEq) g_negr[G + p] = j;
            }
            base += sTot;
            __syncthreads();
        }
        __syncthreads();
        if (tid == 0) {
            __threadfence();
            atomicExch(&g_selDone, 1);
        }
        return;
    }

    // ---- ROI pool: 4 rois per block, spin on topk done ----
    if (tid == 0) {
        while (atomicAdd(&g_selDone, 0) == 0) {}
    }
    __syncthreads();
    int j = (blk - SEL_ROI0_) * 4 + (tid >> 8);
    int c = tid & 255;
    int sel = (j < NPOS_) ? g_posr[j] : g_negr[j - NPOS_];
    int b = sel / R_;
    float t  = nms_reg[sel*4+0], l = nms_reg[sel*4+1];
    float bb = nms_reg[sel*4+2], r = nms_reg[sel*4+3];
    const float* fb = g_fmt + (size_t)b * H_ * W_ * C_;
    for (int p = 0; p < PP_*PP_; p++) {
        int py = p / PP_, px = p % PP_;
        float gy = (py + 0.5f) / (float)PP_;
        float gx = (px + 0.5f) / (float)PP_;
        float y = fminf(fmaxf(t + gy * (bb - t), 0.f), (float)(H_-1));
        float x = fminf(fmaxf(l + gx * (r  - l), 0.f), (float)(W_-1));
        int y0 = (int)floorf(y), x0 = (int)floorf(x);
        int y1 = min(y0 + 1, H_-1), x1 = min(x0 + 1, W_-1);
        float wy = y - (float)y0, wx = x - (float)x0;
        float v00 = fb[(y0*W_+x0)*C_ + c];
        float v01 = fb[(y0*W_+x1)*C_ + c];
        float v10 = fb[(y1*W_+x0)*C_ + c];
        float v11 = fb[(y1*W_+x1)*C_ + c];
        float v = v00*(1.f-wy)*(1.f-wx) + v01*(1.f-wy)*wx
                + v10*wy*(1.f-wx)       + v11*wy*wx;
        __nv_bfloat16 h = __float2bfloat16(v);
        int o = j*D_ + p*C_ + c;
        g_Ahi[o] = h;
        g_Alo[o] = __float2bfloat16(v - __bfloat162float(h));
    }
}

// ---------------- mma.sync GEMM: BM128 BN64 BK32, 3-stage, split-K=8, warp tile 64x16 ----------------
__device__ __forceinline__ void ldsm_x4(uint32_t* r, uint32_t addr) {
    asm volatile("ldmatrix.sync.aligned.m8n8.x4.shared.b16 {%0,%1,%2,%3}, [%4];"
        : "=r"(r[0]), "=r"(r[1]), "=r"(r[2]), "=r"(r[3]) : "r"(addr));
}
__device__ __forceinline__ void mma16816(float* d, const uint32_t* a, const uint32_t* b) {
    asm volatile("mma.sync.aligned.m16n8k16.row.col.f32.bf16.bf16.f32 "
        "{%0,%1,%2,%3}, {%4,%5,%6,%7}, {%8,%9}, {%0,%1,%2,%3};"
        : "+f"(d[0]), "+f"(d[1]), "+f"(d[2]), "+f"(d[3])
        : "r"(a[0]), "r"(a[1]), "r"(a[2]), "r"(a[3]), "r"(b[0]), "r"(b[1]));
}
__device__ __forceinline__ void cp16(uint32_t saddr, const void* gaddr) {
    asm volatile("cp.async.cg.shared.global [%0], [%1], 16;" :: "r"(saddr), "l"(gaddr));
}

__global__ void __launch_bounds__(256, 2) gemm_mma_kernel(const float* __restrict__ W1) {
    extern __shared__ char smem[];
    uint32_t sb = smem_u32(smem);
    int tid = threadIdx.x, wid = tid >> 5, lane = tid & 31;
    int n0 = blockIdx.x * 64;
    int m0 = blockIdx.y * 128;
    int kt = blockIdx.z;
    int kbase = kt * KPC_;
    int wm = wid >> 2, wn = wid & 3;     // warp tile 64x16

    const uint4* bAhi = (const uint4*)g_Ahi + (size_t)m0 * (D_/8);
    const uint4* bAlo = (const uint4*)g_Alo + (size_t)m0 * (D_/8);

    int a0r = tid >> 2,          a0q = tid & 3;
    int a1r = (tid + 256) >> 2,  a1q = tid & 3;
    int b0r = tid >> 4, b0q = tid & 15;

    auto load_stage = [&](int it) {
        uint32_t sg = sb + (it % NSTG_) * STAGE_;
        int kk = kbase + it*BK_;
        int kq = kk >> 3;
        cp16(sg +          a0r*80 + a0q*16, bAhi + (size_t)a0r*(D_/8) + kq + a0q);
        cp16(sg +          a1r*80 + a1q*16, bAhi + (size_t)a1r*(D_/8) + kq + a1q);
        cp16(sg + ATILE_ + a0r*80 + a0q*16, bAlo + (size_t)a0r*(D_/8) + kq + a0q);
        cp16(sg + ATILE_ + a1r*80 + a1q*16, bAlo + (size_t)a1r*(D_/8) + kq + a1q);
        uint32_t bg = sg + 2*ATILE_;
        cp16(bg + b0r*(BPADW_*4) + b0q*16,      W1 + (size_t)(kk + b0r)*DH_ + n0 + b0q*4);
        cp16(bg + (b0r+16)*(BPADW_*4) + b0q*16, W1 + (size_t)(kk + b0r+16)*DH_ + n0 + b0q*4);
        asm volatile("cp.async.commit_group;");
    };

    float acc[4][2][4];
    #pragma unroll
    for (int i = 0; i < 4; i++)
        #pragma unroll
        for (int j = 0; j < 2; j++)
            #pragma unroll
            for (int q = 0; q < 4; q++) acc[i][j][q] = 0.f;

    load_stage(0);
    load_stage(1);

    for (int it = 0; it < NIT_; it++) {
        asm volatile("cp.async.wait_group 1;");
        __syncthreads();
        if (it + 2 < NIT_) load_stage(it + 2);
        else asm volatile("cp.async.commit_group;");

        uint32_t sg = sb + (it % NSTG_) * STAGE_;
        uint32_t aHiB = sg, aLoB = sg + ATILE_;
        const float* sBf = (const float*)(smem + (it % NSTG_) * STAGE_ + 2*ATILE_);

        #pragma unroll
        for (int ks = 0; ks < 2; ks++) {
            int acol = ks*16 + ((lane >> 4) & 1) * 8;
            uint32_t ahi[4][4], alo[4][4], bhi[2][2], blo[2][2];
            #pragma unroll
            for (int mt = 0; mt < 4; mt++) {
                int arow = wm*64 + mt*16 + (lane & 15);
                uint32_t off = arow*80 + acol*2;
                ldsm_x4(ahi[mt], aHiB + off);
                ldsm_x4(alo[mt], aLoB + off);
            }
            #pragma unroll
            for (int nt = 0; nt < 2; nt++) {
                int nn = wn*16 + nt*8 + (lane >> 2);
                #pragma unroll
                for (int rg = 0; rg < 2; rg++) {
                    int kk2 = ks*16 + (lane & 3)*2 + rg*8;
                    float v0 = sBf[(kk2+0)*BPADW_ + nn];
                    float v1 = sBf[(kk2+1)*BPADW_ + nn];
                    uint32_t hreg;
                    asm("cvt.rn.bf16x2.f32 %0, %1, %2;" : "=r"(hreg) : "f"(v1), "f"(v0));
                    float h0 = __uint_as_float(hreg << 16);
                    float h1 = __uint_as_float(hreg & 0xFFFF0000u);
                    uint32_t lreg;
                    asm("cvt.rn.bf16x2.f32 %0, %1, %2;" : "=r"(lreg) : "f"(v1-h1), "f"(v0-h0));
                    bhi[nt][rg] = hreg;
                    blo[nt][rg] = lreg;
                }
            }
            #pragma unroll
            for (int mt = 0; mt < 4; mt++)
                #pragma unroll
                for (int nt = 0; nt < 2; nt++) {
                    mma16816(acc[mt][nt], ahi[mt], bhi[nt]);
                    mma16816(acc[mt][nt], ahi[mt], blo[nt]);
                    mma16816(acc[mt][nt], alo[mt], bhi[nt]);
                }
        }
    }

    float* outp = g_partial[kt];
    int g = lane >> 2, qc = (lane & 3) * 2;
    #pragma unroll
    for (int mt = 0; mt < 4; mt++) {
        #pragma unroll
        for (int nt = 0; nt < 2; nt++) {
            int row = m0 + wm*64 + mt*16 + g;
            int col = n0 + wn*16 + nt*8 + qc;
            *(float2*)&outp[(size_t)row*DH_ + col]     = make_float2(acc[mt][nt][0], acc[mt][nt][1]);
            *(float2*)&outp[(size_t)(row+8)*DH_ + col] = make_float2(acc[mt][nt][2], acc[mt][nt][3]);
        }
    }
}

// ---------------- fused: reduce partials + bias + relu + heads (coalesced weights) ----------------
__global__ void __launch_bounds__(1024) mlp_tail_kernel(const float* __restrict__ b1,
                                const float* __restrict__ br, const float* __restrict__ bc) {
    __shared__ float h[DH_];
    int row = blockIdx.x;
    int tid = threadIdx.x;              // 1024
    float s = b1[tid];
    #pragma unroll
    for (int k = 0; k < KT_; k++)
        s += g_partial[k][(size_t)row*DH_ + tid];
    h[tid] = fmaxf(s, 0.f);
    __syncthreads();
    int wid = tid >> 5, lane = tid & 31;
    if (wid < 4 + NCLS_) {
        const float* wrow = (wid < 4) ? &g_WrT[wid*DH_] : &g_WcT[(wid-4)*DH_];
        float sum = 0.f;
        #pragma unroll 8
        for (int k = lane; k < DH_; k += 32) sum += h[k] * wrow[k];
        #pragma unroll
        for (int d = 16; d; d >>= 1) sum += __shfl_down_sync(0xffffffffu, sum, d);
        if (lane == 0) {
            if (wid < 4) g_rreg[row*4 + wid] = sum + br[wid];
            else         g_rcls[row*NCLS_ + (wid-4)] = sum + bc[wid-4];
        }
    }
}

// ---------------- finalize ----------------
__device__ float blockReduceSum512(float v, float* sbuf) {
    int tid = threadIdx.x;
    sbuf[tid] = v; __syncthreads();
    for (int s = 256; s > 0; s >>= 1) {
        if (tid < s) sbuf[tid] += sbuf[tid + s];
        __syncthreads();
    }
    float r = sbuf[0]; __syncthreads();
    return r;
}

__global__ void finalize_kernel(const float* __restrict__ nms_reg,
                                const float* __restrict__ bboxes,
                                const int*   __restrict__ classes,
                                const float* __restrict__ anchors,
                                const float* __restrict__ rpn_reg,
                                const float* __restrict__ rpn_cls,
                                float* __restrict__ out) {
    __shared__ float sbuf[512];
    int tid = threadIdx.x;

    float a = 0.f;
    if (tid < 380) {
        int i = (tid < 128) ? g_pos[tid] : g_neg[tid - 128];
        float x = rpn_cls[i];
        float lbl = (tid < 128) ? 1.f : 0.f;
        a = fmaxf(x, 0.f) - x * lbl + log1pf(expf(-fabsf(x)));
    }
    float rpnCls = blockReduceSum512(a, sbuf) / 380.f;

    float bsum = 0.f;
    {
        int jj = tid >> 2, c = tid & 3;
        int i = g_pos[jj];
        int b = i / A_;
        int aidx = i - b * A_;
        float pred = rpn_reg[i*4 + c];
        float tgt = bboxes[(b*T_ + g_tidx[i])*4 + c] - anchors[aidx*4 + c];
        float d = fabsf(pred - tgt);
        bsum = (d < 1.f) ? 0.5f*d*d : d - 0.5f;
    }
    float rpnReg = blockReduceSum512(bsum, sbuf) / 512.f / 4.f;

    float csum = 0.f, accsum = 0.f;
    if (tid < 256) {
        int j = tid;
        int cls = 0;
        if (j < NPOS_) {
            int i = g_posr[j];
            int b = i / R_;
            cls = classes[b*T_ + g_ridx[i]];
        }
        const float* row = &g_rcls[j*NCLS_];
        float mx = row[0];
        #pragma unroll
        for (int c = 1; c < NCLS_; c++) mx = fmaxf(mx, row[c]);
        float se = 0.f;
        #pragma unroll
        for (int c = 0; c < NCLS_; c++) se += expf(row[c] - mx);
        float lse = mx + logf(se);
        csum = lse - row[cls];
        if (j < NPOS_) {
            int am = 0; float bv = row[0];
            #pragma unroll
            for (int c = 1; c < NCLS_; c++) if (row[c] > bv) { bv = row[c]; am = c; }
            accsum = (am == cls) ? 1.f : 0.f;
        }
    }
    float rcnnCls = blockReduceSum512(csum, sbuf) / 256.f;
    float acc     = blockReduceSum512(accsum, sbuf) / (float)NPOS_;

    float dsl = 0.f, dab = 0.f;
    if (tid < NPOS_*4) {
        int jj = tid >> 2, c = tid & 3;
        int i = g_posr[jj];
        int b = i / R_;
        float v = nms_reg[i*4 + c];
        float rounded = (c < 2) ? floorf(v * 16.f) / 16.f : ceilf(v * 16.f) / 16.f;
        float mb = bboxes[(b*T_ + g_ridx[i])*4 + c];
        float tgt = mb - rounded;
        float pr = g_rreg[jj*4 + c];
        float d = fabsf(pr - tgt);
        dsl = (d < 1.f) ? 0.5f*d*d : d - 0.5f;
        dab = d;
    }
    float rcnnReg = blockReduceSum512(dsl, sbuf) / (float)NPOS_ / 4.f;
    float offset  = blockReduceSum512(dab, sbuf) / (float)NPOS_ / 4.f;

    if (tid == 0) {
        out[0] = rpnCls;
        out[1] = rpnReg;
        out[2] = rcnnCls;
        out[3] = rcnnReg;
        out[4] = acc;
        out[5] = offset;
    }
}

// ---------------- launch ----------------
extern "C" void kernel_launch(void* const* d_in, const int* in_sizes, int n_in,
                              void* d_out, int out_size) {
    const float* nms_reg  = (const float*)d_in[0];
    const float* fm       = (const float*)d_in[2];
    const float* bboxes   = (const float*)d_in[3];
    const int*   classes  = (const int*)  d_in[4];
    const float* anchors  = (const float*)d_in[5];
    const float* rpn_reg  = (const float*)d_in[6];
    const float* rpn_cls  = (const float*)d_in[7];
    const float* W1       = (const float*)d_in[8];
    const float* b1       = (const float*)d_in[9];
    const float* Wr       = (const float*)d_in[10];
    const float* br       = (const float*)d_in[11];
    const float* Wc       = (const float*)d_in[12];
    const float* bc       = (const float*)d_in[13];
    float* out = (float*)d_out;

    cudaFuncSetAttribute(gemm_mma_kernel, cudaFuncAttributeMaxDynamicSharedMemorySize, SMEM_GEMM_);

    prep_kernel<<<PB_TOTAL, 256>>>(fm, bboxes, anchors, nms_reg, Wr, Wc);
    sel_kernel<<<SEL_NBLK_, 1024>>>(nms_reg);
    gemm_mma_kernel<<<dim3(16, 2, KT_), 256, SMEM_GEMM_>>>(W1);
    mlp_tail_kernel<<<256, 1024>>>(b1, br, bc);
    finalize_kernel<<<1, 512>>>(nms_reg, bboxes, classes, anchors, rpn_reg, rpn_cls, out);
}